// round 6
// baseline (speedup 1.0000x reference)
#include <cuda_runtime.h>

#define B_  2
#define T_  2048
#define C_  1024
#define H_  16
#define HD_ 64

__device__ float g_Q[(size_t)B_ * H_ * T_ * HD_];
__device__ float g_K[(size_t)B_ * H_ * T_ * HD_];
__device__ float g_V[(size_t)B_ * H_ * T_ * HD_];
__device__ float g_Y[(size_t)B_ * T_ * C_];
// tf32-prerounded operands
__device__ float g_Xt[(size_t)B_ * T_ * C_];
__device__ float g_Wqt[(size_t)C_ * C_];
__device__ float g_Wkt[(size_t)C_ * C_];
__device__ float g_Wvt[(size_t)C_ * C_];
__device__ float g_Wpt[(size_t)C_ * C_];

// ---------------------------------------------------------------------------
// helpers
// ---------------------------------------------------------------------------
__device__ __forceinline__ unsigned f2tf32(float f) {
    unsigned u; asm("cvt.rna.tf32.f32 %0, %1;" : "=r"(u) : "f"(f)); return u;
}
__device__ __forceinline__ uint4 cvt4_tf32(float4 f) {
    uint4 u; u.x = f2tf32(f.x); u.y = f2tf32(f.y);
    u.z = f2tf32(f.z); u.w = f2tf32(f.w); return u;
}
__device__ __forceinline__ float ex2f(float x) {
    float y; asm("ex2.approx.f32 %0, %1;" : "=f"(y) : "f"(x)); return y;
}
__device__ __forceinline__ void mma8(float* c, const unsigned* a, const unsigned* b) {
    asm volatile(
        "mma.sync.aligned.m16n8k8.row.col.f32.tf32.tf32.f32 "
        "{%0,%1,%2,%3}, {%4,%5,%6,%7}, {%8,%9}, {%0,%1,%2,%3};"
        : "+f"(c[0]), "+f"(c[1]), "+f"(c[2]), "+f"(c[3])
        : "r"(a[0]), "r"(a[1]), "r"(a[2]), "r"(a[3]), "r"(b[0]), "r"(b[1]));
}
__device__ __forceinline__ unsigned smem_u32(const void* p) {
    unsigned a;
    asm("{ .reg .u64 t; cvta.to.shared.u64 t, %1; cvt.u32.u64 %0, t; }"
        : "=r"(a) : "l"(p));
    return a;
}
__device__ __forceinline__ void cpa16(unsigned s, const void* g) {
    asm volatile("cp.async.ca.shared.global [%0], [%1], 16;"
                 :: "r"(s), "l"(g) : "memory");
}
#define CP_COMMIT() asm volatile("cp.async.commit_group;" ::: "memory")
#define CP_WAIT(n)  asm volatile("cp.async.wait_group %0;" :: "n"(n) : "memory")

// ---------------------------------------------------------------------------
// prep: round x + weights to tf32 values (fp32 storage)
// grid (4096, 5): y=0 -> x (4M), y=1..4 -> weights (1M, blocks>=1024 idle)
// ---------------------------------------------------------------------------
__global__ void __launch_bounds__(256) prep_round(
    const float* __restrict__ x,  const float* __restrict__ wq,
    const float* __restrict__ wk, const float* __restrict__ wv,
    const float* __restrict__ wp)
{
    const int y = blockIdx.y;
    const float* src; float* dst; size_t n;
    if (y == 0)      { src = x;  dst = g_Xt;  n = (size_t)B_ * T_ * C_; }
    else if (y == 1) { src = wq; dst = g_Wqt; n = (size_t)C_ * C_; }
    else if (y == 2) { src = wk; dst = g_Wkt; n = (size_t)C_ * C_; }
    else if (y == 3) { src = wv; dst = g_Wvt; n = (size_t)C_ * C_; }
    else             { src = wp; dst = g_Wpt; n = (size_t)C_ * C_; }
    size_t i = ((size_t)blockIdx.x * 256 + threadIdx.x) * 4;
    if (i < n) {
        float4 v = *(const float4*)(src + i);
        uint4 u = cvt4_tf32(v);
        *(float4*)(dst + i) = *(float4*)&u;
    }
}

// ---------------------------------------------------------------------------
// tf32 mma GEMM, cp.async double-buffered. Inputs pre-rounded.
// CTA 128x128, BK=32, 256 thr (8 warps, warp tile 64x32).
// smem strides: A 36, B 136.  scatter=1 -> write tf32-rounded [b,h,t,d].
// ---------------------------------------------------------------------------
#define GEMM_SMEM (17920 * 4)

__device__ __forceinline__ void tc_gemm(
    const float* __restrict__ A, const float* __restrict__ W,
    const float* __restrict__ bias, float* __restrict__ Out, int scatter)
{
    extern __shared__ float sf[];
    float* As0 = sf;            // 128*36
    float* As1 = sf + 4608;
    float* Bs0 = sf + 9216;     // 32*136
    float* Bs1 = sf + 13568;
    const unsigned sbase = smem_u32(sf);
    const unsigned uA[2] = { sbase, sbase + 4608u * 4u };
    const unsigned uB[2] = { sbase + 9216u * 4u, sbase + 13568u * 4u };

    const int tid = threadIdx.x;
    const int lane = tid & 31, wid = tid >> 5;
    const int g = lane >> 2, t = lane & 3;
    const int wm = wid >> 2, wn = wid & 3;
    const int bm0 = blockIdx.y * 128, bn0 = blockIdx.x * 128;

    const int ar0 = tid >> 3, ac0 = (tid & 7) * 4;
    const int br0 = tid >> 5, bc0 = (tid & 31) * 4;

    float acc[4][4][4];
#pragma unroll
    for (int mt = 0; mt < 4; mt++)
#pragma unroll
        for (int nt = 0; nt < 4; nt++)
#pragma unroll
            for (int e = 0; e < 4; e++) acc[mt][nt][e] = 0.f;

    auto issue = [&](int c) {
        const int k0 = c * 32, buf = c & 1;
#pragma unroll
        for (int r = 0; r < 4; r++) {
            const int arow = ar0 + r * 32;
            cpa16(uA[buf] + (unsigned)(arow * 36 + ac0) * 4u,
                  A + (size_t)(bm0 + arow) * 1024 + k0 + ac0);
            const int brow = br0 + r * 8;
            cpa16(uB[buf] + (unsigned)(brow * 136 + bc0) * 4u,
                  W + (size_t)(k0 + brow) * 1024 + bn0 + bc0);
        }
        CP_COMMIT();
    };

    issue(0);
    for (int c = 0; c < 32; c++) {
        if (c < 31) { issue(c + 1); CP_WAIT(1); }
        else        { CP_WAIT(0); }
        __syncthreads();

        const float* Ab = (c & 1) ? As1 : As0;
        const float* Bb = (c & 1) ? Bs1 : Bs0;
#pragma unroll
        for (int kk = 0; kk < 4; kk++) {
            unsigned af[4][4], bf[4][2];
#pragma unroll
            for (int mt = 0; mt < 4; mt++) {
                const float* p = Ab + (wm * 64 + mt * 16 + g) * 36 + kk * 8 + t;
                af[mt][0] = __float_as_uint(p[0]);
                af[mt][1] = __float_as_uint(p[8 * 36]);
                af[mt][2] = __float_as_uint(p[4]);
                af[mt][3] = __float_as_uint(p[8 * 36 + 4]);
            }
#pragma unroll
            for (int nt = 0; nt < 4; nt++) {
                const float* p = Bb + (kk * 8 + t) * 136 + wn * 32 + nt * 8 + g;
                bf[nt][0] = __float_as_uint(p[0]);
                bf[nt][1] = __float_as_uint(p[4 * 136]);
            }
#pragma unroll
            for (int mt = 0; mt < 4; mt++)
#pragma unroll
                for (int nt = 0; nt < 4; nt++)
                    mma8(acc[mt][nt], af[mt], bf[nt]);
        }
        __syncthreads();
    }

#pragma unroll
    for (int mt = 0; mt < 4; mt++) {
#pragma unroll
        for (int nt = 0; nt < 4; nt++) {
            const int col = bn0 + wn * 32 + nt * 8 + 2 * t;
            const float b0 = bias[col], b1 = bias[col + 1];
#pragma unroll
            for (int h = 0; h < 2; h++) {
                const int row = bm0 + wm * 64 + mt * 16 + h * 8 + g;
                float v0 = acc[mt][nt][2 * h] + b0;
                float v1 = acc[mt][nt][2 * h + 1] + b1;
                if (scatter) {
                    // store tf32-rounded (consumed by tf32 attention)
                    float2 v = make_float2(__uint_as_float(f2tf32(v0)),
                                           __uint_as_float(f2tf32(v1)));
                    const int hh = col >> 6, d = col & 63;
                    const int bb = row >> 11, tt = row & 2047;
                    *(float2*)(Out + ((((size_t)bb * H_ + hh) * T_ + tt) << 6) + d) = v;
                } else {
                    *(float2*)(Out + (size_t)row * C_ + col) = make_float2(v0, v1);
                }
            }
        }
    }
}

__global__ void __launch_bounds__(256) qkv_mma()
{
    const float* W; float* O;
    if (blockIdx.z == 0)      { W = g_Wqt; O = g_Q; }
    else if (blockIdx.z == 1) { W = g_Wkt; O = g_K; }
    else                      { W = g_Wvt; O = g_V; }
    // biases are zero-extended via gb (set below in launch through cmem? use g_bias)
    extern __shared__ float sf[];
    (void)sf;
    // bias pointers passed via __device__? simpler: biases stored in g_bias
    // (declared below) — see kernel_launch.
    // NOTE: actual body invoked from wrapper below.
}

// bias staging (avoids extra kernel params in qkv path)
__device__ float g_bq[C_], g_bk[C_], g_bv[C_];

__global__ void __launch_bounds__(256) qkv_mma2()
{
    const float* W; float* O; const float* bb;
    if (blockIdx.z == 0)      { W = g_Wqt; O = g_Q; bb = g_bq; }
    else if (blockIdx.z == 1) { W = g_Wkt; O = g_K; bb = g_bk; }
    else                      { W = g_Wvt; O = g_V; bb = g_bv; }
    tc_gemm(g_Xt, W, bb, O, 1);
}

__global__ void __launch_bounds__(256) copy_bias(
    const float* __restrict__ bq, const float* __restrict__ bk,
    const float* __restrict__ bv)
{
    int i = blockIdx.x * 256 + threadIdx.x;
    if (i < C_) { g_bq[i] = bq[i]; g_bk[i] = bk[i]; g_bv[i] = bv[i]; }
}

__global__ void __launch_bounds__(256) proj_mma(
    const float* __restrict__ bp, float* __restrict__ Out)
{
    tc_gemm(g_Y, g_Wpt, bp, Out, 0);
}

// ---------------------------------------------------------------------------
// Flash attention, tf32 mma, cp.async K/V double-buffer (operands pre-rounded).
// CTA = 128 q-rows, 256 thr (8 warps), warp = 16 q-rows; k-tiles of 64.
// smem floats: Qs 128x68 @0, Ks[2] 64x68 @8704/@13056, Vs[2] 64x72 @17408/@22016,
// Ps 8x(16x68) @26624. Total 35328 floats = 141312 B.
// ---------------------------------------------------------------------------
#define FLASH_SMEM (35328 * 4)
#define CSC 0.18033688011112042f  // 1/sqrt(64) * log2(e)

__global__ void __launch_bounds__(256) flash_mma()
{
    extern __shared__ float sf[];
    float* Qs = sf;
    float* Ksb[2] = { sf + 8704, sf + 13056 };
    float* Vsb[2] = { sf + 17408, sf + 22016 };
    float* Ps = sf + 26624 + (threadIdx.x >> 5) * 1088;
    const unsigned sbase = smem_u32(sf);

    const int tid = threadIdx.x;
    const int lane = tid & 31, w = tid >> 5;
    const int g = lane >> 2, t = lane & 3;

    const int qblk = (int)gridDim.x - 1 - (int)blockIdx.x;  // heavy first
    const int q0 = qblk * 128;
    const int nkt = 2 * qblk + 2;
    const int hh = blockIdx.y, b = blockIdx.z;
    const size_t base = ((size_t)(b * H_ + hh)) * T_ * HD_;
    const float* Qg = g_Q + base;
    const float* Kg = g_K + base;
    const float* Vg = g_V + base;

    const int lrow0 = tid >> 4;
    const int lcq = (tid & 15) * 4;

    auto issue_kv = [&](int kt) {
        const int buf = kt & 1;
        const unsigned uK = sbase + (8704u + (unsigned)buf * 4352u) * 4u;
        const unsigned uV = sbase + (17408u + (unsigned)buf * 4608u) * 4u;
#pragma unroll
        for (int r = 0; r < 4; r++) {
            const int row = lrow0 + r * 16;
            cpa16(uK + (unsigned)(row * 68 + lcq) * 4u,
                  Kg + (size_t)(kt * 64 + row) * HD_ + lcq);
            cpa16(uV + (unsigned)(row * 72 + lcq) * 4u,
                  Vg + (size_t)(kt * 64 + row) * HD_ + lcq);
        }
        CP_COMMIT();
    };

    // prologue: KV(0), then Q
    issue_kv(0);
#pragma unroll
    for (int r = 0; r < 8; r++) {
        int fi = tid + r * 256;
        int row = fi >> 4, cq = (fi & 15) * 4;
        cpa16(sbase + (unsigned)(row * 68 + cq) * 4u,
              Qg + (size_t)(q0 + row) * HD_ + cq);
    }
    CP_COMMIT();

    float oacc[8][4];
    float mrow[2], lrow[2];
    mrow[0] = mrow[1] = -1e30f;
    lrow[0] = lrow[1] = 0.f;
#pragma unroll
    for (int nt = 0; nt < 8; nt++)
#pragma unroll
        for (int e = 0; e < 4; e++) oacc[nt][e] = 0.f;

    for (int kt = 0; kt < nkt; kt++) {
        if (kt + 1 < nkt) { issue_kv(kt + 1); CP_WAIT(1); }
        else              { CP_WAIT(0); }
        __syncthreads();

        // warps 0-3: final k-tile entirely above the causal diagonal
        if (!(kt == nkt - 1 && w < 4)) {
            const float* Ks = Ksb[kt & 1];
            const float* Vs = Vsb[kt & 1];

            float sacc[8][4];
#pragma unroll
            for (int nt = 0; nt < 8; nt++)
#pragma unroll
                for (int e = 0; e < 4; e++) sacc[nt][e] = 0.f;

#pragma unroll
            for (int kk = 0; kk < 8; kk++) {
                unsigned af[4], bf[8][2];
                {
                    const float* p = Qs + (16 * w + g) * 68 + kk * 8 + t;
                    af[0] = __float_as_uint(p[0]);
                    af[1] = __float_as_uint(p[8 * 68]);
                    af[2] = __float_as_uint(p[4]);
                    af[3] = __float_as_uint(p[8 * 68 + 4]);
                }
#pragma unroll
                for (int nt = 0; nt < 8; nt++) {
                    const float* p = Ks + (nt * 8 + g) * 68 + kk * 8 + t;
                    bf[nt][0] = __float_as_uint(p[0]);
                    bf[nt][1] = __float_as_uint(p[4]);
                }
#pragma unroll
                for (int nt = 0; nt < 8; nt++)
                    mma8(sacc[nt], af, bf[nt]);
            }

            if (kt >= nkt - 2) {
#pragma unroll
                for (int nt = 0; nt < 8; nt++)
#pragma unroll
                    for (int e = 0; e < 4; e++) {
                        const int col = kt * 64 + nt * 8 + 2 * t + (e & 1);
                        const int row = q0 + 16 * w + 8 * (e >> 1) + g;
                        float v = sacc[nt][e] * CSC;
                        sacc[nt][e] = (col > row) ? -1e30f : v;
                    }
            } else {
#pragma unroll
                for (int nt = 0; nt < 8; nt++)
#pragma unroll
                    for (int e = 0; e < 4; e++) sacc[nt][e] *= CSC;
            }

#pragma unroll
            for (int h = 0; h < 2; h++) {
                float mx = -1e30f;
#pragma unroll
                for (int nt = 0; nt < 8; nt++)
                    mx = fmaxf(mx, fmaxf(sacc[nt][2 * h], sacc[nt][2 * h + 1]));
                mx = fmaxf(mx, __shfl_xor_sync(0xffffffffu, mx, 1));
                mx = fmaxf(mx, __shfl_xor_sync(0xffffffffu, mx, 2));
                const float mo = mrow[h];
                const float mn = fmaxf(mo, mx);
                const float alpha = ex2f(mo - mn);
                mrow[h] = mn;
                float rs = 0.f;
#pragma unroll
                for (int nt = 0; nt < 8; nt++) {
                    float p0 = __uint_as_float(f2tf32(ex2f(sacc[nt][2 * h] - mn)));
                    float p1 = __uint_as_float(f2tf32(ex2f(sacc[nt][2 * h + 1] - mn)));
                    rs += p0 + p1;
                    *(float2*)(Ps + (8 * h + g) * 68 + nt * 8 + 2 * t) =
                        make_float2(p0, p1);
                    oacc[nt][2 * h]     *= alpha;
                    oacc[nt][2 * h + 1] *= alpha;
                }
                rs += __shfl_xor_sync(0xffffffffu, rs, 1);
                rs += __shfl_xor_sync(0xffffffffu, rs, 2);
                lrow[h] = lrow[h] * alpha + rs;
            }
            __syncwarp();

#pragma unroll
            for (int kk = 0; kk < 8; kk++) {
                unsigned af[4], bf[8][2];
                {
                    const float* p = Ps + g * 68 + kk * 8 + t;
                    af[0] = __float_as_uint(p[0]);
                    af[1] = __float_as_uint(p[8 * 68]);
                    af[2] = __float_as_uint(p[4]);
                    af[3] = __float_as_uint(p[8 * 68 + 4]);
                }
#pragma unroll
                for (int nt = 0; nt < 8; nt++) {
                    const float* p = Vs + (kk * 8 + t) * 72 + nt * 8 + g;
                    bf[nt][0] = __float_as_uint(p[0]);
                    bf[nt][1] = __float_as_uint(p[4 * 72]);
                }
#pragma unroll
                for (int nt = 0; nt < 8; nt++)
                    mma8(oacc[nt], af, bf[nt]);
            }
            __syncwarp();
        }
        __syncthreads();  // all reads done before next tile overwrites buffers
    }

    // normalize + write [b,t,c] tf32-rounded (consumed by tf32 proj)
#pragma unroll
    for (int h = 0; h < 2; h++) {
        const float inv = 1.0f / lrow[h];
        const int row = q0 + 16 * w + 8 * h + g;
#pragma unroll
        for (int nt = 0; nt < 8; nt++) {
            const int d = nt * 8 + 2 * t;
            float2 v = make_float2(
                __uint_as_float(f2tf32(oacc[nt][2 * h] * inv)),
                __uint_as_float(f2tf32(oacc[nt][2 * h + 1] * inv)));
            *(float2*)(g_Y + ((size_t)b * T_ + row) * C_ + hh * HD_ + d) = v;
        }
    }
}

extern "C" void kernel_launch(void* const* d_in, const int* in_sizes, int n_in,
                              void* d_out, int out_size)
{
    const float* x  = (const float*)d_in[0];
    const float* Wq = (const float*)d_in[1];
    const float* bq = (const float*)d_in[2];
    const float* Wk = (const float*)d_in[3];
    const float* bk = (const float*)d_in[4];
    const float* Wv = (const float*)d_in[5];
    const float* bv = (const float*)d_in[6];
    const float* Wp = (const float*)d_in[7];
    const float* bp = (const float*)d_in[8];

    cudaFuncSetAttribute(qkv_mma2, cudaFuncAttributeMaxDynamicSharedMemorySize, GEMM_SMEM);
    cudaFuncSetAttribute(proj_mma, cudaFuncAttributeMaxDynamicSharedMemorySize, GEMM_SMEM);
    cudaFuncSetAttribute(flash_mma, cudaFuncAttributeMaxDynamicSharedMemorySize, FLASH_SMEM);

    prep_round<<<dim3(4096, 5), 256>>>(x, Wq, Wk, Wv, Wp);
    copy_bias<<<4, 256>>>(bq, bk, bv);

    qkv_mma2<<<dim3(8, 32, 3), 256, GEMM_SMEM>>>();
    flash_mma<<<dim3(16, 16, 2), 256, FLASH_SMEM>>>();
    proj_mma<<<dim3(8, 32), 256, GEMM_SMEM>>>(bp, (float*)d_out);
}